// round 4
// baseline (speedup 1.0000x reference)
#include <cuda_runtime.h>

#define B_      32
#define H_      256
#define W_      256
#define TW      30          // output tile
#define TH      30
#define RW      32          // delta region = (TW+2) x (TH+2)
#define RH      32
#define CWD     34          // comb tile = (TW+4) x (TH+4)
#define CHT     34
#define NTHR    256
#define N_STEPS 10

typedef unsigned long long u64;

// Ping-pong state, channels-last [B][H][W][16] as float4 x4
__device__ float4 g_state0[(size_t)B_ * H_ * W_ * 4];
__device__ float4 g_state1[(size_t)B_ * H_ * W_ * 4];
// Fused perceive->up1 weights: (W_up1 @ W_perceive): [16][17][9], bias [16]
__device__ float g_wf[16 * 17 * 9];
__device__ float g_bf[16];

__device__ __forceinline__ u64 pack2(float lo, float hi) {
    u64 r;
    asm("mov.b64 %0, {%1, %2};" : "=l"(r) : "f"(lo), "f"(hi));
    return r;
}
__device__ __forceinline__ void unpack2(u64 v, float& lo, float& hi) {
    asm("mov.b64 {%0, %1}, %2;" : "=f"(lo), "=f"(hi) : "l"(v));
}
__device__ __forceinline__ void fma2(u64& acc, u64 a, u64 b) {
    asm("fma.rn.f32x2 %0, %1, %2, %0;" : "+l"(acc) : "l"(a), "l"(b));
}
__device__ __forceinline__ float sigmoidf_(float z) {
    return 1.0f / (1.0f + __expf(-z));
}

struct SM {
    float comb[CHT][CWD][17];     // x + state, halo 2
    float del [RH][RW][17];       // delta, halo 1 (16 used, stride 17)
    ulonglong2 wf [17][9][4];     // fused conv weights, out-ch pairs x2
    ulonglong2 wt [33][9][4];     // tau weights
    ulonglong2 wu2[16][4];        // up2
    u64 bf2[8];                   // fused bias pairs
    u64 bu22[8];
    u64 bt2[8];                   // b_tau_conv + b_tau
};

// ---- prep: fold up1 into perceive (both linear; relu is after up1) ----
extern "C" __global__ void fuse_weights(const float* __restrict__ wp,
                                        const float* __restrict__ bp,
                                        const float* __restrict__ w1,
                                        const float* __restrict__ b1)
{
    int i = blockIdx.x * blockDim.x + threadIdx.x;
    if (i < 16 * 153) {
        int o = i / 153, ck = i % 153;
        float s = 0.f;
        #pragma unroll
        for (int m = 0; m < 32; m++) s += w1[o * 32 + m] * wp[m * 153 + ck];
        g_wf[i] = s;
    }
    if (i < 16) {
        float s = b1[i];
        #pragma unroll
        for (int m = 0; m < 32; m++) s += w1[i * 32 + m] * bp[m];
        g_bf[i] = s;
    }
}

extern "C" __global__ void __launch_bounds__(NTHR)
nca_step(const float*  __restrict__ x,
         const float4* __restrict__ sIn,
         float4*       __restrict__ sOut,
         const float* __restrict__ w_up2,  const float* __restrict__ b_up2,
         const float* __restrict__ w_tau,  const float* __restrict__ b_tauc,
         const float* __restrict__ b_tau)
{
    extern __shared__ char smraw[];
    SM& sm = *reinterpret_cast<SM*>(smraw);

    const int tid = threadIdx.x;
    const int x0 = blockIdx.x * TW;
    const int y0 = blockIdx.y * TH;
    const int b  = blockIdx.z;

    // ---- pack weights into shared ----
    for (int i = tid; i < 17 * 9 * 4; i += NTHR) {         // fused conv
        int q = i & 3, k = (i >> 2) % 9, c = i / 36;
        int o = 4 * q;
        sm.wf[c][k][q] = make_ulonglong2(
            pack2(g_wf[(o + 0) * 153 + c * 9 + k], g_wf[(o + 1) * 153 + c * 9 + k]),
            pack2(g_wf[(o + 2) * 153 + c * 9 + k], g_wf[(o + 3) * 153 + c * 9 + k]));
    }
    for (int i = tid; i < 33 * 9 * 4; i += NTHR) {         // tau
        int q = i & 3, k = (i >> 2) % 9, c = i / 36;
        int o = 4 * q;
        sm.wt[c][k][q] = make_ulonglong2(
            pack2(w_tau[(o + 0) * 297 + c * 9 + k], w_tau[(o + 1) * 297 + c * 9 + k]),
            pack2(w_tau[(o + 2) * 297 + c * 9 + k], w_tau[(o + 3) * 297 + c * 9 + k]));
    }
    for (int i = tid; i < 16 * 4; i += NTHR) {             // up2
        int q = i & 3, ci = i >> 2;
        int o = 4 * q;
        sm.wu2[ci][q] = make_ulonglong2(
            pack2(w_up2[(o + 0) * 16 + ci], w_up2[(o + 1) * 16 + ci]),
            pack2(w_up2[(o + 2) * 16 + ci], w_up2[(o + 3) * 16 + ci]));
    }
    if (tid < 8) {
        sm.bf2[tid] = pack2(g_bf[2 * tid], g_bf[2 * tid + 1]);
    } else if (tid < 16) {
        int j = tid - 8;
        sm.bu22[j] = pack2(b_up2[2 * j], b_up2[2 * j + 1]);
    } else if (tid < 24) {
        int j = tid - 16;
        sm.bt2[j] = pack2(b_tauc[2 * j] + b_tau[2 * j],
                          b_tauc[2 * j + 1] + b_tau[2 * j + 1]);
    }

    // ---- load combined = [x, state] tile with halo 2 (zero padded) ----
    for (int p = tid; p < CHT * CWD; p += NTHR) {
        int cy = p / CWD, cx = p % CWD;
        int gy = y0 - 2 + cy, gx = x0 - 2 + cx;
        float* dst = &sm.comb[cy][cx][0];
        if ((unsigned)gy < H_ && (unsigned)gx < W_) {
            long pix = ((long)(b * H_ + gy)) * W_ + gx;
            dst[0] = x[pix];
            float4 s0 = sIn[pix * 4 + 0];
            float4 s1 = sIn[pix * 4 + 1];
            float4 s2 = sIn[pix * 4 + 2];
            float4 s3 = sIn[pix * 4 + 3];
            dst[1] = s0.x;  dst[2] = s0.y;  dst[3] = s0.z;  dst[4] = s0.w;
            dst[5] = s1.x;  dst[6] = s1.y;  dst[7] = s1.z;  dst[8] = s1.w;
            dst[9] = s2.x;  dst[10] = s2.y; dst[11] = s2.z; dst[12] = s2.w;
            dst[13] = s3.x; dst[14] = s3.y; dst[15] = s3.z; dst[16] = s3.w;
        } else {
            #pragma unroll
            for (int c = 0; c < 17; c++) dst[c] = 0.f;
        }
    }
    __syncthreads();

    // ---- stage 2: fused conv(17->16)+relu+up2(16->16) over 32x32 region,
    //      one 2x2 quad per thread (16x16 quads == 256 threads) ----
    {
        const int qx = tid & 15, qy = tid >> 4;
        const int rx = 2 * qx, ry = 2 * qy;          // region coords of px(0,0)
        const int gx0 = x0 - 1 + rx;
        const int gy0 = y0 - 1 + ry;
        const float* cb = &sm.comb[ry][rx][0];       // 4x4 window base

        u64 acc[4][8];
        #pragma unroll
        for (int p = 0; p < 4; p++)
            #pragma unroll
            for (int j = 0; j < 8; j++) acc[p][j] = sm.bf2[j];

        #pragma unroll 1
        for (int c = 0; c < 17; c++) {
            const float* cc = cb + c;
            u64 pv[16];
            #pragma unroll
            for (int i = 0; i < 4; i++)
                #pragma unroll
                for (int j = 0; j < 4; j++) {
                    float v = cc[(i * CWD + j) * 17];
                    pv[i * 4 + j] = pack2(v, v);
                }
            #pragma unroll
            for (int k = 0; k < 9; k++) {
                const int dy = k / 3, dx = k % 3;
                u64 v00 = pv[dy * 4 + dx],       v01 = pv[dy * 4 + dx + 1];
                u64 v10 = pv[(dy + 1) * 4 + dx], v11 = pv[(dy + 1) * 4 + dx + 1];
                #pragma unroll
                for (int q = 0; q < 4; q++) {
                    ulonglong2 w = sm.wf[c][k][q];
                    fma2(acc[0][2 * q],     w.x, v00);
                    fma2(acc[0][2 * q + 1], w.y, v00);
                    fma2(acc[1][2 * q],     w.x, v01);
                    fma2(acc[1][2 * q + 1], w.y, v01);
                    fma2(acc[2][2 * q],     w.x, v10);
                    fma2(acc[2][2 * q + 1], w.y, v10);
                    fma2(acc[3][2 * q],     w.x, v11);
                    fma2(acc[3][2 * q + 1], w.y, v11);
                }
            }
        }

        // relu + up2, two pixels at a time (shared weight loads)
        #pragma unroll
        for (int pp = 0; pp < 2; pp++) {
            float h0[16], h1[16];
            #pragma unroll
            for (int j = 0; j < 8; j++) {
                float a, bq;
                unpack2(acc[2 * pp][j], a, bq);
                h0[2 * j] = fmaxf(a, 0.f); h0[2 * j + 1] = fmaxf(bq, 0.f);
                unpack2(acc[2 * pp + 1][j], a, bq);
                h1[2 * j] = fmaxf(a, 0.f); h1[2 * j + 1] = fmaxf(bq, 0.f);
            }
            u64 d0[8], d1[8];
            #pragma unroll
            for (int j = 0; j < 8; j++) { d0[j] = sm.bu22[j]; d1[j] = sm.bu22[j]; }
            #pragma unroll
            for (int ci = 0; ci < 16; ci++) {
                u64 p0 = pack2(h0[ci], h0[ci]);
                u64 p1 = pack2(h1[ci], h1[ci]);
                #pragma unroll
                for (int q = 0; q < 4; q++) {
                    ulonglong2 w = sm.wu2[ci][q];
                    fma2(d0[2 * q],     w.x, p0);
                    fma2(d0[2 * q + 1], w.y, p0);
                    fma2(d1[2 * q],     w.x, p1);
                    fma2(d1[2 * q + 1], w.y, p1);
                }
            }
            #pragma unroll
            for (int s = 0; s < 2; s++) {
                const int p = 2 * pp + s;
                const int a = p >> 1, bq = p & 1;
                const bool vp = (unsigned)(gy0 + a) < H_ && (unsigned)(gx0 + bq) < W_;
                float* dd = &sm.del[ry + a][rx + bq][0];
                const u64* dsel = s ? d1 : d0;
                #pragma unroll
                for (int j = 0; j < 8; j++) {
                    float e0, e1;
                    unpack2(dsel[j], e0, e1);
                    dd[2 * j]     = vp ? e0 : 0.f;
                    dd[2 * j + 1] = vp ? e1 : 0.f;
                }
            }
        }
    }
    __syncthreads();

    // ---- stage 3: tau conv3x3 (33->16) + gated blend, 2x2 quads (15x15) ----
    if (tid < 15 * 15) {
        const int ox = 2 * (tid % 15);
        const int oy = 2 * (tid / 15);
        const int gx0 = x0 + ox;
        const int gy0 = y0 + oy;

        const float* cb = &sm.comb[oy + 1][ox + 1][0];  // 4x4 comb window base
        const float* db = &sm.del [oy][ox][0];          // 4x4 del window base

        u64 acc[4][8];
        #pragma unroll
        for (int p = 0; p < 4; p++)
            #pragma unroll
            for (int j = 0; j < 8; j++) acc[p][j] = sm.bt2[j];

        #pragma unroll 1
        for (int c = 0; c < 17; c++) {      // x + state channels
            const float* cc = cb + c;
            u64 pv[16];
            #pragma unroll
            for (int i = 0; i < 4; i++)
                #pragma unroll
                for (int j = 0; j < 4; j++) {
                    float v = cc[(i * CWD + j) * 17];
                    pv[i * 4 + j] = pack2(v, v);
                }
            #pragma unroll
            for (int k = 0; k < 9; k++) {
                const int dy = k / 3, dx = k % 3;
                u64 v00 = pv[dy * 4 + dx],       v01 = pv[dy * 4 + dx + 1];
                u64 v10 = pv[(dy + 1) * 4 + dx], v11 = pv[(dy + 1) * 4 + dx + 1];
                #pragma unroll
                for (int q = 0; q < 4; q++) {
                    ulonglong2 w = sm.wt[c][k][q];
                    fma2(acc[0][2 * q],     w.x, v00);
                    fma2(acc[0][2 * q + 1], w.y, v00);
                    fma2(acc[1][2 * q],     w.x, v01);
                    fma2(acc[1][2 * q + 1], w.y, v01);
                    fma2(acc[2][2 * q],     w.x, v10);
                    fma2(acc[2][2 * q + 1], w.y, v10);
                    fma2(acc[3][2 * q],     w.x, v11);
                    fma2(acc[3][2 * q + 1], w.y, v11);
                }
            }
        }
        #pragma unroll 1
        for (int c = 0; c < 16; c++) {      // delta channels
            const float* cc = db + c;
            u64 pv[16];
            #pragma unroll
            for (int i = 0; i < 4; i++)
                #pragma unroll
                for (int j = 0; j < 4; j++) {
                    float v = cc[(i * RW + j) * 17];
                    pv[i * 4 + j] = pack2(v, v);
                }
            #pragma unroll
            for (int k = 0; k < 9; k++) {
                const int dy = k / 3, dx = k % 3;
                u64 v00 = pv[dy * 4 + dx],       v01 = pv[dy * 4 + dx + 1];
                u64 v10 = pv[(dy + 1) * 4 + dx], v11 = pv[(dy + 1) * 4 + dx + 1];
                #pragma unroll
                for (int q = 0; q < 4; q++) {
                    ulonglong2 w = sm.wt[17 + c][k][q];
                    fma2(acc[0][2 * q],     w.x, v00);
                    fma2(acc[0][2 * q + 1], w.y, v00);
                    fma2(acc[1][2 * q],     w.x, v01);
                    fma2(acc[1][2 * q + 1], w.y, v01);
                    fma2(acc[2][2 * q],     w.x, v10);
                    fma2(acc[2][2 * q + 1], w.y, v10);
                    fma2(acc[3][2 * q],     w.x, v11);
                    fma2(acc[3][2 * q + 1], w.y, v11);
                }
            }
        }

        // blend + store, per pixel of the quad
        #pragma unroll
        for (int p = 0; p < 4; p++) {
            const int a = p >> 1, bq = p & 1;
            const int gy = gy0 + a, gx = gx0 + bq;
            if (gy < H_ && gx < W_) {
                const float* st = &sm.comb[oy + 2 + a][ox + 2 + bq][1];
                const float* dl = &sm.del [oy + 1 + a][ox + 1 + bq][0];
                float nv[16];
                #pragma unroll
                for (int j = 0; j < 8; j++) {
                    float z0, z1;
                    unpack2(acc[p][j], z0, z1);
                    float b0 = fminf(fmaxf(sigmoidf_(z0), 0.01f), 0.99f);
                    float b1 = fminf(fmaxf(sigmoidf_(z1), 0.01f), 0.99f);
                    nv[2 * j]     = b0 * st[2 * j]     + (1.f - b0) * dl[2 * j];
                    nv[2 * j + 1] = b1 * st[2 * j + 1] + (1.f - b1) * dl[2 * j + 1];
                }
                long pix = ((long)(b * H_ + gy)) * W_ + gx;
                sOut[pix * 4 + 0] = make_float4(nv[0],  nv[1],  nv[2],  nv[3]);
                sOut[pix * 4 + 1] = make_float4(nv[4],  nv[5],  nv[6],  nv[7]);
                sOut[pix * 4 + 2] = make_float4(nv[8],  nv[9],  nv[10], nv[11]);
                sOut[pix * 4 + 3] = make_float4(nv[12], nv[13], nv[14], nv[15]);
            }
        }
    }
}

extern "C" __global__ void zero_state() {
    long i = (long)blockIdx.x * blockDim.x + threadIdx.x;
    long n = (long)B_ * H_ * W_ * 4;
    if (i < n) g_state0[i] = make_float4(0.f, 0.f, 0.f, 0.f);
}

extern "C" __global__ void readout(const float4* __restrict__ s,
                                   const float* __restrict__ w_read,
                                   const float* __restrict__ b_read,
                                   float* __restrict__ out)
{
    long i = (long)blockIdx.x * blockDim.x + threadIdx.x;
    if (i >= (long)B_ * H_ * W_) return;
    float4 a0 = s[i * 4 + 0];
    float4 a1 = s[i * 4 + 1];
    float4 a2 = s[i * 4 + 2];
    float4 a3 = s[i * 4 + 3];
    float acc = b_read[0];
    acc += a0.x * w_read[0]  + a0.y * w_read[1]  + a0.z * w_read[2]  + a0.w * w_read[3];
    acc += a1.x * w_read[4]  + a1.y * w_read[5]  + a1.z * w_read[6]  + a1.w * w_read[7];
    acc += a2.x * w_read[8]  + a2.y * w_read[9]  + a2.z * w_read[10] + a2.w * w_read[11];
    acc += a3.x * w_read[12] + a3.y * w_read[13] + a3.z * w_read[14] + a3.w * w_read[15];
    out[i] = 1.0f / (1.0f + __expf(-acc));
}

extern "C" void kernel_launch(void* const* d_in, const int* in_sizes, int n_in,
                              void* d_out, int out_size)
{
    const float* x   = (const float*)d_in[0];
    const float* wp  = (const float*)d_in[1];
    const float* bp  = (const float*)d_in[2];
    const float* wu1 = (const float*)d_in[3];
    const float* bu1 = (const float*)d_in[4];
    const float* wu2 = (const float*)d_in[5];
    const float* bu2 = (const float*)d_in[6];
    const float* wt  = (const float*)d_in[7];
    const float* btc = (const float*)d_in[8];
    const float* bt  = (const float*)d_in[9];
    const float* wr  = (const float*)d_in[10];
    const float* br  = (const float*)d_in[11];
    float* out = (float*)d_out;

    cudaFuncSetAttribute(nca_step, cudaFuncAttributeMaxDynamicSharedMemorySize,
                         (int)sizeof(SM));

    float4 *s0, *s1;
    cudaGetSymbolAddress((void**)&s0, g_state0);
    cudaGetSymbolAddress((void**)&s1, g_state1);

    fuse_weights<<<10, 256>>>(wp, bp, wu1, bu1);

    long n4 = (long)B_ * H_ * W_ * 4;
    zero_state<<<(int)((n4 + 255) / 256), 256>>>();

    dim3 grid((W_ + TW - 1) / TW, (H_ + TH - 1) / TH, B_);
    float4* cur = s0;
    float4* nxt = s1;
    for (int s = 0; s < N_STEPS; s++) {
        nca_step<<<grid, NTHR, sizeof(SM)>>>(x, cur, nxt,
                                             wu2, bu2, wt, btc, bt);
        float4* t = cur; cur = nxt; nxt = t;
    }

    long npix = (long)B_ * H_ * W_;
    readout<<<(int)((npix + 255) / 256), 256>>>(cur, wr, br, out);
}

// round 5
// speedup vs baseline: 1.7262x; 1.7262x over previous
#include <cuda_runtime.h>

#define B_      32
#define H_      256
#define W_      256
#define TW      30          // output tile width
#define TH      30          // output tile height
#define RW      32          // stage-2 (delta) region = (TW+2) x (TH+2)
#define RH      32
#define CWD     34          // comb tile = (TW+4) x (TH+4)
#define CHT     34
#define NTHR    512
#define N_STEPS 10

typedef unsigned long long u64;

// Ping-pong state, channels-last [B][H][W][16] as float4 x4
__device__ float4 g_state0[(size_t)B_ * H_ * W_ * 4];
__device__ float4 g_state1[(size_t)B_ * H_ * W_ * 4];
// Fused perceive->up1 weights: (W_up1 @ W_perceive): [16][17][9], bias [16]
__device__ float g_wf[16 * 17 * 9];
__device__ float g_bf[16];

__device__ __forceinline__ u64 pack2(float lo, float hi) {
    u64 r;
    asm("mov.b64 %0, {%1, %2};" : "=l"(r) : "f"(lo), "f"(hi));
    return r;
}
__device__ __forceinline__ void unpack2(u64 v, float& lo, float& hi) {
    asm("mov.b64 {%0, %1}, %2;" : "=f"(lo), "=f"(hi) : "l"(v));
}
__device__ __forceinline__ void fma2(u64& acc, u64 a, u64 b) {
    asm("fma.rn.f32x2 %0, %1, %2, %0;" : "+l"(acc) : "l"(a), "l"(b));
}
__device__ __forceinline__ float sigmoidf_(float z) {
    return 1.0f / (1.0f + __expf(-z));
}

struct SM {
    float comb[CHT][CWD][17];     // x + state, halo 2 (stride 17 conflict-free)
    float del [RH][RW][17];       // delta, halo 1 (16 used, stride 17)
    ulonglong2 wf [17][9][4];     // fused conv 17->16 weights (out-ch quads)
    ulonglong2 wt [33][9][4];     // tau weights
    ulonglong2 wu2[16][4];        // up2
    u64 bf2[8];                   // fused bias pairs
    u64 bu22[8];
    u64 bt2[8];                   // b_tau_conv + b_tau
};

// ---- prep: fold up1 into perceive (both linear; relu is after up1) ----
extern "C" __global__ void fuse_weights(const float* __restrict__ wp,
                                        const float* __restrict__ bp,
                                        const float* __restrict__ w1,
                                        const float* __restrict__ b1)
{
    int i = blockIdx.x * blockDim.x + threadIdx.x;
    if (i < 16 * 153) {
        int o = i / 153, ck = i % 153;
        float s = 0.f;
        #pragma unroll
        for (int m = 0; m < 32; m++) s += w1[o * 32 + m] * wp[m * 153 + ck];
        g_wf[i] = s;
    }
    if (i < 16) {
        float s = b1[i];
        #pragma unroll
        for (int m = 0; m < 32; m++) s += w1[i * 32 + m] * bp[m];
        g_bf[i] = s;
    }
}

extern "C" __global__ void __launch_bounds__(NTHR, 1)
nca_step(const float*  __restrict__ x,
         const float4* __restrict__ sIn,
         float4*       __restrict__ sOut,
         const float* __restrict__ w_up2,  const float* __restrict__ b_up2,
         const float* __restrict__ w_tau,  const float* __restrict__ b_tauc,
         const float* __restrict__ b_tau)
{
    extern __shared__ char smraw[];
    SM& sm = *reinterpret_cast<SM*>(smraw);

    const int tid = threadIdx.x;
    const int x0 = blockIdx.x * TW;
    const int y0 = blockIdx.y * TH;
    const int b  = blockIdx.z;

    // ---- pack weights into shared ----
    for (int i = tid; i < 17 * 9 * 4; i += NTHR) {         // fused conv
        int q = i & 3, k = (i >> 2) % 9, c = i / 36;
        int o = 4 * q;
        sm.wf[c][k][q] = make_ulonglong2(
            pack2(g_wf[(o + 0) * 153 + c * 9 + k], g_wf[(o + 1) * 153 + c * 9 + k]),
            pack2(g_wf[(o + 2) * 153 + c * 9 + k], g_wf[(o + 3) * 153 + c * 9 + k]));
    }
    for (int i = tid; i < 33 * 9 * 4; i += NTHR) {         // tau
        int q = i & 3, k = (i >> 2) % 9, c = i / 36;
        int o = 4 * q;
        sm.wt[c][k][q] = make_ulonglong2(
            pack2(w_tau[(o + 0) * 297 + c * 9 + k], w_tau[(o + 1) * 297 + c * 9 + k]),
            pack2(w_tau[(o + 2) * 297 + c * 9 + k], w_tau[(o + 3) * 297 + c * 9 + k]));
    }
    for (int i = tid; i < 16 * 4; i += NTHR) {             // up2
        int q = i & 3, ci = i >> 2;
        int o = 4 * q;
        sm.wu2[ci][q] = make_ulonglong2(
            pack2(w_up2[(o + 0) * 16 + ci], w_up2[(o + 1) * 16 + ci]),
            pack2(w_up2[(o + 2) * 16 + ci], w_up2[(o + 3) * 16 + ci]));
    }
    if (tid < 8) {
        sm.bf2[tid] = pack2(g_bf[2 * tid], g_bf[2 * tid + 1]);
    } else if (tid < 16) {
        int j = tid - 8;
        sm.bu22[j] = pack2(b_up2[2 * j], b_up2[2 * j + 1]);
    } else if (tid < 24) {
        int j = tid - 16;
        sm.bt2[j] = pack2(b_tauc[2 * j] + b_tau[2 * j],
                          b_tauc[2 * j + 1] + b_tau[2 * j + 1]);
    }

    // ---- load combined = [x, state] tile with halo 2 (zero padded) ----
    for (int p = tid; p < CHT * CWD; p += NTHR) {
        int cy = p / CWD, cx = p % CWD;
        int gy = y0 - 2 + cy, gx = x0 - 2 + cx;
        float* dst = &sm.comb[cy][cx][0];
        if ((unsigned)gy < H_ && (unsigned)gx < W_) {
            long pix = ((long)(b * H_ + gy)) * W_ + gx;
            dst[0] = x[pix];
            float4 s0 = sIn[pix * 4 + 0];
            float4 s1 = sIn[pix * 4 + 1];
            float4 s2 = sIn[pix * 4 + 2];
            float4 s3 = sIn[pix * 4 + 3];
            dst[1] = s0.x;  dst[2] = s0.y;  dst[3] = s0.z;  dst[4] = s0.w;
            dst[5] = s1.x;  dst[6] = s1.y;  dst[7] = s1.z;  dst[8] = s1.w;
            dst[9] = s2.x;  dst[10] = s2.y; dst[11] = s2.z; dst[12] = s2.w;
            dst[13] = s3.x; dst[14] = s3.y; dst[15] = s3.z; dst[16] = s3.w;
        } else {
            #pragma unroll
            for (int c = 0; c < 17; c++) dst[c] = 0.f;
        }
    }
    __syncthreads();

    // ---- stage 2: fused conv(17->16)+relu+up2(16->16) over 32x32 region,
    //      2 vertical px / thread (512 threads == 32x16 jobs) ----
    {
        const int rx  = tid & 31;        // 0..31
        const int ryp = tid >> 5;        // 0..15
        const int ry2 = 2 * ryp;         // region rows ry2, ry2+1
        const int gx  = x0 - 1 + rx;
        const int gy0 = y0 - 1 + ry2;
        const bool v0 = (unsigned)gx < W_ && (unsigned)gy0 < H_;
        const bool v1 = (unsigned)gx < W_ && (unsigned)(gy0 + 1) < H_;

        const float* cb = &sm.comb[ry2][rx][0];   // window top-left for px0

        u64 a0[8], a1[8];
        #pragma unroll
        for (int j = 0; j < 8; j++) { a0[j] = sm.bf2[j]; a1[j] = sm.bf2[j]; }

        #pragma unroll 1
        for (int c = 0; c < 17; c++) {
            const float* cc = cb + c;
            u64 pv[12];   // rows 0..3 x cols 0..2, duplicated pairs
            #pragma unroll
            for (int i = 0; i < 4; i++)
                #pragma unroll
                for (int j = 0; j < 3; j++) {
                    float v = cc[(i * CWD + j) * 17];
                    pv[i * 3 + j] = pack2(v, v);
                }
            #pragma unroll
            for (int k = 0; k < 9; k++) {
                u64 pa = pv[k];       // (dy)*3+dx  == k
                u64 pb = pv[k + 3];   // (dy+1)*3+dx
                #pragma unroll
                for (int q = 0; q < 4; q++) {
                    ulonglong2 w = sm.wf[c][k][q];
                    fma2(a0[2 * q],     w.x, pa);
                    fma2(a0[2 * q + 1], w.y, pa);
                    fma2(a1[2 * q],     w.x, pb);
                    fma2(a1[2 * q + 1], w.y, pb);
                }
            }
        }

        // relu
        float h0[16], h1[16];
        #pragma unroll
        for (int j = 0; j < 8; j++) {
            float a, bq;
            unpack2(a0[j], a, bq);
            h0[2 * j] = fmaxf(a, 0.f); h0[2 * j + 1] = fmaxf(bq, 0.f);
            unpack2(a1[j], a, bq);
            h1[2 * j] = fmaxf(a, 0.f); h1[2 * j + 1] = fmaxf(bq, 0.f);
        }

        // up2: 1x1 16 -> 16 = delta (both pixels share weight loads)
        u64 d0[8], d1[8];
        #pragma unroll
        for (int j = 0; j < 8; j++) { d0[j] = sm.bu22[j]; d1[j] = sm.bu22[j]; }
        #pragma unroll
        for (int ci = 0; ci < 16; ci++) {
            u64 p0 = pack2(h0[ci], h0[ci]);
            u64 p1 = pack2(h1[ci], h1[ci]);
            #pragma unroll
            for (int q = 0; q < 4; q++) {
                ulonglong2 w = sm.wu2[ci][q];
                fma2(d0[2 * q],     w.x, p0);
                fma2(d0[2 * q + 1], w.y, p0);
                fma2(d1[2 * q],     w.x, p1);
                fma2(d1[2 * q + 1], w.y, p1);
            }
        }

        float* dd0 = &sm.del[ry2][rx][0];
        float* dd1 = &sm.del[ry2 + 1][rx][0];
        #pragma unroll
        for (int j = 0; j < 8; j++) {
            float e0, e1, f0, f1;
            unpack2(d0[j], e0, e1);
            unpack2(d1[j], f0, f1);
            dd0[2 * j]     = v0 ? e0 : 0.f;
            dd0[2 * j + 1] = v0 ? e1 : 0.f;
            dd1[2 * j]     = v1 ? f0 : 0.f;
            dd1[2 * j + 1] = v1 ? f1 : 0.f;
        }
    }
    __syncthreads();

    // ---- stage 3: tau conv3x3 (33->16) + gated blend, 2 px / thread ----
    if (tid < TW * (TH / 2)) {   // 30 * 15 = 450 jobs
        const int ox  = tid % TW;
        const int oyp = tid / TW;
        const int oy2 = 2 * oyp;
        const int gx  = x0 + ox;
        const int gy0 = y0 + oy2;
        const bool v0 = gx < W_ && gy0 < H_;
        const bool v1 = gx < W_ && (gy0 + 1) < H_;

        const float* cb = &sm.comb[oy2 + 1][ox + 1][0];   // comb window base
        const float* db = &sm.del [oy2][ox][0];           // del window base

        u64 a0[8], a1[8];
        #pragma unroll
        for (int j = 0; j < 8; j++) { a0[j] = sm.bt2[j]; a1[j] = sm.bt2[j]; }

        #pragma unroll 1
        for (int c = 0; c < 17; c++) {   // x + state channels from comb
            const float* cc = cb + c;
            u64 pv[12];
            #pragma unroll
            for (int i = 0; i < 4; i++)
                #pragma unroll
                for (int j = 0; j < 3; j++) {
                    float v = cc[(i * CWD + j) * 17];
                    pv[i * 3 + j] = pack2(v, v);
                }
            #pragma unroll
            for (int k = 0; k < 9; k++) {
                u64 pa = pv[k];
                u64 pb = pv[k + 3];
                #pragma unroll
                for (int q = 0; q < 4; q++) {
                    ulonglong2 w = sm.wt[c][k][q];
                    fma2(a0[2 * q],     w.x, pa);
                    fma2(a0[2 * q + 1], w.y, pa);
                    fma2(a1[2 * q],     w.x, pb);
                    fma2(a1[2 * q + 1], w.y, pb);
                }
            }
        }
        #pragma unroll 1
        for (int c = 0; c < 16; c++) {   // delta channels from del
            const float* cc = db + c;
            u64 pv[12];
            #pragma unroll
            for (int i = 0; i < 4; i++)
                #pragma unroll
                for (int j = 0; j < 3; j++) {
                    float v = cc[(i * RW + j) * 17];
                    pv[i * 3 + j] = pack2(v, v);
                }
            #pragma unroll
            for (int k = 0; k < 9; k++) {
                u64 pa = pv[k];
                u64 pb = pv[k + 3];
                #pragma unroll
                for (int q = 0; q < 4; q++) {
                    ulonglong2 w = sm.wt[17 + c][k][q];
                    fma2(a0[2 * q],     w.x, pa);
                    fma2(a0[2 * q + 1], w.y, pa);
                    fma2(a1[2 * q],     w.x, pb);
                    fma2(a1[2 * q + 1], w.y, pb);
                }
            }
        }

        // blend: new = beta*state + (1-beta)*delta for both pixels
        const float* st0 = &sm.comb[oy2 + 2][ox + 2][1];
        const float* st1 = &sm.comb[oy2 + 3][ox + 2][1];
        const float* dl0 = &sm.del [oy2 + 1][ox + 1][0];
        const float* dl1 = &sm.del [oy2 + 2][ox + 1][0];

        float nv0[16], nv1[16];
        #pragma unroll
        for (int j = 0; j < 8; j++) {
            float z00, z01, z10, z11;
            unpack2(a0[j], z00, z01);
            unpack2(a1[j], z10, z11);
            float b00 = fminf(fmaxf(sigmoidf_(z00), 0.01f), 0.99f);
            float b01 = fminf(fmaxf(sigmoidf_(z01), 0.01f), 0.99f);
            float b10 = fminf(fmaxf(sigmoidf_(z10), 0.01f), 0.99f);
            float b11 = fminf(fmaxf(sigmoidf_(z11), 0.01f), 0.99f);
            nv0[2 * j]     = b00 * st0[2 * j]     + (1.f - b00) * dl0[2 * j];
            nv0[2 * j + 1] = b01 * st0[2 * j + 1] + (1.f - b01) * dl0[2 * j + 1];
            nv1[2 * j]     = b10 * st1[2 * j]     + (1.f - b10) * dl1[2 * j];
            nv1[2 * j + 1] = b11 * st1[2 * j + 1] + (1.f - b11) * dl1[2 * j + 1];
        }
        if (v0) {
            long pix = ((long)(b * H_ + gy0)) * W_ + gx;
            sOut[pix * 4 + 0] = make_float4(nv0[0],  nv0[1],  nv0[2],  nv0[3]);
            sOut[pix * 4 + 1] = make_float4(nv0[4],  nv0[5],  nv0[6],  nv0[7]);
            sOut[pix * 4 + 2] = make_float4(nv0[8],  nv0[9],  nv0[10], nv0[11]);
            sOut[pix * 4 + 3] = make_float4(nv0[12], nv0[13], nv0[14], nv0[15]);
        }
        if (v1) {
            long pix = ((long)(b * H_ + gy0 + 1)) * W_ + gx;
            sOut[pix * 4 + 0] = make_float4(nv1[0],  nv1[1],  nv1[2],  nv1[3]);
            sOut[pix * 4 + 1] = make_float4(nv1[4],  nv1[5],  nv1[6],  nv1[7]);
            sOut[pix * 4 + 2] = make_float4(nv1[8],  nv1[9],  nv1[10], nv1[11]);
            sOut[pix * 4 + 3] = make_float4(nv1[12], nv1[13], nv1[14], nv1[15]);
        }
    }
}

extern "C" __global__ void zero_state() {
    long i = (long)blockIdx.x * blockDim.x + threadIdx.x;
    long n = (long)B_ * H_ * W_ * 4;
    if (i < n) g_state0[i] = make_float4(0.f, 0.f, 0.f, 0.f);
}

extern "C" __global__ void readout(const float4* __restrict__ s,
                                   const float* __restrict__ w_read,
                                   const float* __restrict__ b_read,
                                   float* __restrict__ out)
{
    long i = (long)blockIdx.x * blockDim.x + threadIdx.x;
    if (i >= (long)B_ * H_ * W_) return;
    float4 a0 = s[i * 4 + 0];
    float4 a1 = s[i * 4 + 1];
    float4 a2 = s[i * 4 + 2];
    float4 a3 = s[i * 4 + 3];
    float acc = b_read[0];
    acc += a0.x * w_read[0]  + a0.y * w_read[1]  + a0.z * w_read[2]  + a0.w * w_read[3];
    acc += a1.x * w_read[4]  + a1.y * w_read[5]  + a1.z * w_read[6]  + a1.w * w_read[7];
    acc += a2.x * w_read[8]  + a2.y * w_read[9]  + a2.z * w_read[10] + a2.w * w_read[11];
    acc += a3.x * w_read[12] + a3.y * w_read[13] + a3.z * w_read[14] + a3.w * w_read[15];
    out[i] = 1.0f / (1.0f + __expf(-acc));
}

extern "C" void kernel_launch(void* const* d_in, const int* in_sizes, int n_in,
                              void* d_out, int out_size)
{
    const float* x   = (const float*)d_in[0];
    const float* wp  = (const float*)d_in[1];
    const float* bp  = (const float*)d_in[2];
    const float* wu1 = (const float*)d_in[3];
    const float* bu1 = (const float*)d_in[4];
    const float* wu2 = (const float*)d_in[5];
    const float* bu2 = (const float*)d_in[6];
    const float* wt  = (const float*)d_in[7];
    const float* btc = (const float*)d_in[8];
    const float* bt  = (const float*)d_in[9];
    const float* wr  = (const float*)d_in[10];
    const float* br  = (const float*)d_in[11];
    float* out = (float*)d_out;

    cudaFuncSetAttribute(nca_step, cudaFuncAttributeMaxDynamicSharedMemorySize,
                         (int)sizeof(SM));

    float4 *s0, *s1;
    cudaGetSymbolAddress((void**)&s0, g_state0);
    cudaGetSymbolAddress((void**)&s1, g_state1);

    fuse_weights<<<10, 256>>>(wp, bp, wu1, bu1);

    long n4 = (long)B_ * H_ * W_ * 4;
    zero_state<<<(int)((n4 + 255) / 256), 256>>>();

    dim3 grid((W_ + TW - 1) / TW, (H_ + TH - 1) / TH, B_);
    float4* cur = s0;
    float4* nxt = s1;
    for (int s = 0; s < N_STEPS; s++) {
        nca_step<<<grid, NTHR, sizeof(SM)>>>(x, cur, nxt,
                                             wu2, bu2, wt, btc, bt);
        float4* t = cur; cur = nxt; nxt = t;
    }

    long npix = (long)B_ * H_ * W_;
    readout<<<(int)((npix + 255) / 256), 256>>>(cur, wr, br, out);
}